// round 3
// baseline (speedup 1.0000x reference)
#include <cuda_runtime.h>
#include <math.h>

#define NPTS   2048
#define NT     256
#define EPT    8
#define NW     (NT/32)
#define MAXPTS 100
#define NBAT   2
#define F_INF  (__int_as_float(0x7f800000))

typedef unsigned long long u64;
typedef unsigned int       u32;

static __device__ __forceinline__ u64 umin64(u64 a, u64 b) { return a < b ? a : b; }
static __device__ __forceinline__ u64 umax64(u64 a, u64 b) { return a > b ? a : b; }

struct Smem {
    float4 spt[NBAT][NPTS];                  // (-2x,-2y,-2z,|x|^2)
    float  sdeath[NBAT][NPTS];
    u64    wred[NBAT][2][NW];                // 16B-aligned (offset 81920)
};

__global__ __launch_bounds__(NT, 1)
void ph_kernel(const float* __restrict__ x,
               const float* __restrict__ filt,
               float* __restrict__ out,
               int B, int F)
{
    extern __shared__ char smraw[];
    Smem* sm = reinterpret_cast<Smem*>(smraw);

    const int tid   = threadIdx.x;
    const int lane  = tid & 31;
    const int wid   = tid >> 5;
    const int gbase = tid << 3;
    const float inf = F_INF;

    const int b0 = blockIdx.x * NBAT;
    int   bidx[NBAT];
    bool  bval[NBAT];
    #pragma unroll
    for (int bb = 0; bb < NBAT; bb++) {
        int gb = b0 + bb;
        bval[bb] = (gb < B);
        bidx[bb] = bval[bb] ? gb : (B - 1);   // clamp: compute on dup, skip writes
    }

    // ---- load both batches: coords in regs, premultiplied float4 in smem ----
    float rx[NBAT][EPT], ry[NBAT][EPT], rz[NBAT][EPT], rsq[NBAT][EPT], mk[NBAT][EPT];
    #pragma unroll
    for (int bb = 0; bb < NBAT; bb++) {
        const float* xb = x + (long)bidx[bb] * NPTS * 3;
        #pragma unroll
        for (int e = 0; e < EPT; e++) {
            int i = gbase + e;
            float a = xb[3*i + 0];
            float c = xb[3*i + 1];
            float d = xb[3*i + 2];
            rx[bb][e] = a; ry[bb][e] = c; rz[bb][e] = d;
            float s = fmaf(a, a, fmaf(c, c, d * d));
            rsq[bb][e] = s; mk[bb][e] = inf;
            sm->spt[bb][i] = make_float4(-2.0f * a, -2.0f * c, -2.0f * d, s);
        }
    }
    __syncthreads();

    // ---- dual interleaved Prim: 2047 rounds, ONE barrier serves BOTH chains ----
    int j[NBAT]; j[0] = 0; j[1] = 0;
    int p = 0;

    #pragma unroll 1
    for (int step = 0; step < NPTS - 1; step++) {
        #pragma unroll
        for (int bb = 0; bb < NBAT; bb++) {
            float4 pj = sm->spt[bb][j[bb]];        // LDS.128 broadcast

            u64 pk[EPT];
            #pragma unroll
            for (int e = 0; e < EPT; e++) {
                int gi = gbase + e;
                bool rem = (gi == j[bb]);
                float rs = rem ? inf : rsq[bb][e];  // permanent poison
                rsq[bb][e] = rs;
                float acc = fmaf(pj.x, rx[bb][e], rs + pj.w);
                acc = fmaf(pj.y, ry[bb][e], acc);
                acc = fmaf(pj.z, rz[bb][e], acc);
                acc = fmaxf(acc, 0.0f);             // >=0 -> u32 bit-order exact
                float m = fminf(mk[bb][e], acc);
                m = rem ? inf : m;
                mk[bb][e] = m;
                pk[e] = ((u64)__float_as_uint(m) << 32) | (u32)gi;
            }
            // 3-level pack tree (value+index argmin, low latency)
            u64 t0 = umin64(pk[0], pk[1]);
            u64 t1 = umin64(pk[2], pk[3]);
            u64 t2 = umin64(pk[4], pk[5]);
            u64 t3 = umin64(pk[6], pk[7]);
            t0 = umin64(t0, t1); t2 = umin64(t2, t3); t0 = umin64(t0, t2);

            u32 vb = (u32)(t0 >> 32);
            u32 ti = (u32)t0;
            u32 r1 = __reduce_min_sync(0xffffffffu, vb);
            u32 ik = (vb == r1) ? ti : 0xffffffffu;
            u32 r2 = __reduce_min_sync(0xffffffffu, ik);
            if (lane == 0) sm->wred[bb][p][wid] = ((u64)r1 << 32) | (u64)r2;
        }
        __syncthreads();

        #pragma unroll
        for (int bb = 0; bb < NBAT; bb++) {
            const ulonglong2* w2 =
                reinterpret_cast<const ulonglong2*>(&sm->wred[bb][p][0]);
            ulonglong2 a = w2[0], c = w2[1], d = w2[2], g = w2[3];
            u64 m0 = umin64(a.x, a.y);
            u64 m1 = umin64(c.x, c.y);
            u64 m2 = umin64(d.x, d.y);
            u64 m3 = umin64(g.x, g.y);
            m0 = umin64(m0, m1); m2 = umin64(m2, m3); m0 = umin64(m0, m2);
            if (tid == 0) sm->sdeath[bb][step] = __uint_as_float((u32)(m0 >> 32));
            j[bb] = (int)(u32)m0;
        }
        p ^= 1;
    }
    __syncthreads();

    // ---- d^2 -> sqrt; pad slot 2047 with +INF ----
    #pragma unroll
    for (int bb = 0; bb < NBAT; bb++) {
        #pragma unroll
        for (int e = 0; e < EPT; e++) {
            int i = gbase + e;
            float d2 = sm->sdeath[bb][i];
            sm->sdeath[bb][i] = (i < NPTS - 1) ? sqrtf(d2) : inf;
        }
    }
    __syncthreads();

    // ---- zero-fill H1/H2 diagram slices and betti rows 1,2 ----
    #pragma unroll
    for (int bb = 0; bb < NBAT; bb++) {
        if (!bval[bb]) continue;
        long dgm_base = (long)bidx[bb] * 3 * MAXPTS * 2;
        long bet_base = (long)B * 3 * MAXPTS * 2 + (long)bidx[bb] * 3 * F;
        for (int i = tid; i < 2 * MAXPTS * 2; i += NT)
            out[dgm_base + MAXPTS * 2 + i] = 0.0f;
        for (int i = tid; i < 2 * F; i += NT)
            out[bet_base + F + i] = 0.0f;
    }

    // ---- Betti-0: warp-halves handle batch A / B in parallel ----
    {
        int bb = tid >> 7;            // 0 or 1
        int lt = tid & 127;
        if (bval[bb]) {
            long bet_base = (long)B * 3 * MAXPTS * 2 + (long)bidx[bb] * 3 * F;
            for (int fi = lt; fi < F; fi += NT / NBAT) {
                float ff = filt[fi];
                int cnt = 0;
                for (int i = 0; i < NPTS; i += 4) {
                    float4 v = *reinterpret_cast<const float4*>(&sm->sdeath[bb][i]);
                    cnt += (v.x <= ff) + (v.y <= ff) + (v.z <= ff) + (v.w <= ff);
                }
                out[bet_base + fi] = (float)(NPTS - cnt);
            }
        }
    }
    __syncthreads();

    // ---- top-100 deaths desc: dual interleaved iterative max extraction ----
    int jp[NBAT]; jp[0] = -1; jp[1] = -1;
    p = 0;
    #pragma unroll 1
    for (int k = 0; k < MAXPTS; k++) {
        #pragma unroll
        for (int bb = 0; bb < NBAT; bb++) {
            u64 pk[EPT];
            #pragma unroll
            for (int e = 0; e < EPT; e++) {
                int gi = gbase + e;
                float v = sm->sdeath[bb][gi];
                v = (gi == jp[bb] || gi == NPTS - 1) ? 0.0f : v;
                pk[e] = ((u64)__float_as_uint(v) << 32) | (u32)gi;
            }
            u64 t0 = umax64(pk[0], pk[1]);
            u64 t1 = umax64(pk[2], pk[3]);
            u64 t2 = umax64(pk[4], pk[5]);
            u64 t3 = umax64(pk[6], pk[7]);
            t0 = umax64(t0, t1); t2 = umax64(t2, t3); t0 = umax64(t0, t2);

            u32 vb = (u32)(t0 >> 32);
            u32 ti = (u32)t0;
            u32 r1 = __reduce_max_sync(0xffffffffu, vb);
            u32 ik = (vb == r1) ? ti : 0u;
            u32 r2 = __reduce_max_sync(0xffffffffu, ik);
            if (lane == 0) sm->wred[bb][p][wid] = ((u64)r1 << 32) | (u64)r2;
        }
        if (tid == 0) {
            #pragma unroll
            for (int bb = 0; bb < NBAT; bb++)
                if (jp[bb] >= 0) sm->sdeath[bb][jp[bb]] = 0.0f;  // persist removal
        }
        __syncthreads();

        #pragma unroll
        for (int bb = 0; bb < NBAT; bb++) {
            const ulonglong2* w2 =
                reinterpret_cast<const ulonglong2*>(&sm->wred[bb][p][0]);
            ulonglong2 a = w2[0], c = w2[1], d = w2[2], g = w2[3];
            u64 m0 = umax64(a.x, a.y);
            u64 m1 = umax64(c.x, c.y);
            u64 m2 = umax64(d.x, d.y);
            u64 m3 = umax64(g.x, g.y);
            m0 = umax64(m0, m1); m2 = umax64(m2, m3); m0 = umax64(m0, m2);
            if (tid == 0 && bval[bb]) {
                long dgm_base = (long)bidx[bb] * 3 * MAXPTS * 2;
                out[dgm_base + 2 * k + 0] = 0.0f;
                out[dgm_base + 2 * k + 1] = __uint_as_float((u32)(m0 >> 32));
            }
            jp[bb] = (int)(u32)m0;
        }
        p ^= 1;
    }
}

extern "C" void kernel_launch(void* const* d_in, const int* in_sizes, int n_in,
                              void* d_out, int out_size)
{
    const float* x    = (const float*)d_in[0];
    const float* filt = (const float*)d_in[1];
    float* out        = (float*)d_out;

    int B = in_sizes[0] / (NPTS * 3);
    int F = in_sizes[1];
    int grid = (B + NBAT - 1) / NBAT;

    cudaFuncSetAttribute(ph_kernel,
                         cudaFuncAttributeMaxDynamicSharedMemorySize,
                         (int)sizeof(Smem));
    ph_kernel<<<grid, NT, sizeof(Smem)>>>(x, filt, out, B, F);
}